// round 4
// baseline (speedup 1.0000x reference)
#include <cuda_runtime.h>
#include <cuda_fp16.h>
#include <stdint.h>

#define D 512               // embedding dim (fixed by problem)
#define EPS 1e-6f
#define NODE_CAP 50000      // capacity of the static fp16 copy

// Runtime index-dtype flag: 1 if edge_index is int64, 0 if int32.
__device__ int g_idx_is64;

// fp16 copy of z: one row = 512 halves = 64 uint4. 51.2 MB.
__device__ uint4 g_zh[(size_t)NODE_CAP * 64];
// exact per-node 1/||z_row|| and sum(z_row), fp32
__device__ float g_inv[NODE_CAP];
__device__ float g_sum[NODE_CAP];

__global__ void detect_idx_dtype_kernel(const int* __restrict__ raw)
{
    __shared__ int any_hi_nonzero;
    if (threadIdx.x == 0) any_hi_nonzero = 0;
    __syncthreads();
    int lo = raw[2 * threadIdx.x];
    int hi = raw[2 * threadIdx.x + 1];
    if (hi != 0 || lo < 0) atomicOr(&any_hi_nonzero, 1);
    __syncthreads();
    if (threadIdx.x == 0) g_idx_is64 = any_hi_nonzero ? 0 : 1;
}

__device__ __forceinline__ uint4 pack8(float4 a, float4 b)
{
    uint4 r;
    __half2 h0 = __floats2half2_rn(a.x, a.y);
    __half2 h1 = __floats2half2_rn(a.z, a.w);
    __half2 h2 = __floats2half2_rn(b.x, b.y);
    __half2 h3 = __floats2half2_rn(b.z, b.w);
    r.x = *reinterpret_cast<unsigned*>(&h0);
    r.y = *reinterpret_cast<unsigned*>(&h1);
    r.z = *reinterpret_cast<unsigned*>(&h2);
    r.w = *reinterpret_cast<unsigned*>(&h3);
    return r;
}

// Pass 1: one warp per node. Stream z row (coalesced float4), compute exact
// fp32 norm and sum, pack fp16 copy (coalesced uint4 stores).
// Layout within a row: uint4 #lane holds float4s {lane, lane+32};
//                      uint4 #lane+32 holds float4s {lane+64, lane+96}.
// Any fixed permutation is fine: dot/norm/sum are permutation-invariant.
__global__ void __launch_bounds__(256)
prep_kernel(const float4* __restrict__ z4, int n_nodes)
{
    int node = (blockIdx.x * blockDim.x + threadIdx.x) >> 5;
    int lane = threadIdx.x & 31;
    if (node >= n_nodes) return;

    const float4* __restrict__ R = z4 + (size_t)node * (D / 4);
    float4 v[4];
#pragma unroll
    for (int j = 0; j < 4; j++) v[j] = R[lane + 32 * j];

    float na2 = 0.f, sa = 0.f;
#pragma unroll
    for (int j = 0; j < 4; j++) {
        float4 a = v[j];
        na2 = fmaf(a.x, a.x, na2);
        na2 = fmaf(a.y, a.y, na2);
        na2 = fmaf(a.z, a.z, na2);
        na2 = fmaf(a.w, a.w, na2);
        sa += a.x + a.y + a.z + a.w;
    }

    uint4* __restrict__ W = g_zh + (size_t)node * 64;
    W[lane]      = pack8(v[0], v[1]);
    W[lane + 32] = pack8(v[2], v[3]);

#pragma unroll
    for (int off = 16; off > 0; off >>= 1) {
        na2 += __shfl_xor_sync(0xFFFFFFFFu, na2, off);
        sa  += __shfl_xor_sync(0xFFFFFFFFu, sa,  off);
    }
    if (lane == 0) {
        g_inv[node] = rsqrtf(na2);
        g_sum[node] = sa;
    }
}

__device__ __forceinline__ float dot8(uint4 a, uint4 b, float acc)
{
    const __half2* ah = reinterpret_cast<const __half2*>(&a);
    const __half2* bh = reinterpret_cast<const __half2*>(&b);
#pragma unroll
    for (int k = 0; k < 4; k++) {
        float2 af = __half22float2(ah[k]);
        float2 bf = __half22float2(bh[k]);
        acc = fmaf(af.x, bf.x, acc);
        acc = fmaf(af.y, bf.y, acc);
    }
    return acc;
}

// Pass 2: one warp per edge. Gather two fp16 rows (1 KB each), dot product
// only; norms/sums come from the precomputed tables.
//   dist^2 = 2 - 2*dot*inva*invb + 2*eps*(sa*inva - sb*invb) + D*eps^2
//   out    = sigmoid(1 - sqrt(max(dist^2, 0)))
__global__ void __launch_bounds__(256)
edge_decoder_h_kernel(const void* __restrict__ edge_index,
                      float* __restrict__ out,
                      int n_edges)
{
    int e = (blockIdx.x * blockDim.x + threadIdx.x) >> 5;
    int lane = threadIdx.x & 31;
    if (e >= n_edges) return;

    long long ia, ib;
    if (g_idx_is64) {
        const long long* ei = (const long long*)edge_index;
        ia = ei[e];
        ib = ei[e + n_edges];
    } else {
        const int* ei = (const int*)edge_index;
        ia = ei[e];
        ib = ei[e + n_edges];
    }

    const uint4* __restrict__ A = g_zh + ia * 64;
    const uint4* __restrict__ B = g_zh + ib * 64;

    uint4 a0 = A[lane], a1 = A[lane + 32];
    uint4 b0 = B[lane], b1 = B[lane + 32];

    float dot = dot8(a0, b0, 0.f);
    dot = dot8(a1, b1, dot);

#pragma unroll
    for (int off = 16; off > 0; off >>= 1)
        dot += __shfl_xor_sync(0xFFFFFFFFu, dot, off);

    if (lane == 0) {
        float inva = g_inv[ia];
        float invb = g_inv[ib];
        float sa   = g_sum[ia];
        float sb   = g_sum[ib];
        float d2 = 2.0f - 2.0f * dot * inva * invb
                 + 2.0f * EPS * (sa * inva - sb * invb)
                 + (float)D * EPS * EPS;
        d2 = fmaxf(d2, 0.0f);
        float v = 1.0f - sqrtf(d2);
        out[e] = 1.0f / (1.0f + __expf(-v));
    }
}

// Fallback (fp32 fused, one warp per edge) if n_nodes exceeds static capacity.
__global__ void __launch_bounds__(256)
edge_decoder_f32_kernel(const float* __restrict__ z,
                        const void* __restrict__ edge_index,
                        float* __restrict__ out,
                        int n_edges)
{
    int e = (blockIdx.x * blockDim.x + threadIdx.x) >> 5;
    int lane = threadIdx.x & 31;
    if (e >= n_edges) return;

    long long ia, ib;
    if (g_idx_is64) {
        const long long* ei = (const long long*)edge_index;
        ia = ei[e];
        ib = ei[e + n_edges];
    } else {
        const int* ei = (const int*)edge_index;
        ia = ei[e];
        ib = ei[e + n_edges];
    }

    const float4* A = reinterpret_cast<const float4*>(z + ia * (long long)D);
    const float4* B = reinterpret_cast<const float4*>(z + ib * (long long)D);

    float dot = 0.f, na2 = 0.f, nb2 = 0.f, sa = 0.f, sb = 0.f;
    float4 av[4], bv[4];
#pragma unroll
    for (int j = 0; j < 4; j++) {
        av[j] = A[lane + 32 * j];
        bv[j] = B[lane + 32 * j];
    }
#pragma unroll
    for (int j = 0; j < 4; j++) {
        float4 a = av[j], b = bv[j];
        dot = fmaf(a.x, b.x, dot); dot = fmaf(a.y, b.y, dot);
        dot = fmaf(a.z, b.z, dot); dot = fmaf(a.w, b.w, dot);
        na2 = fmaf(a.x, a.x, na2); na2 = fmaf(a.y, a.y, na2);
        na2 = fmaf(a.z, a.z, na2); na2 = fmaf(a.w, a.w, na2);
        nb2 = fmaf(b.x, b.x, nb2); nb2 = fmaf(b.y, b.y, nb2);
        nb2 = fmaf(b.z, b.z, nb2); nb2 = fmaf(b.w, b.w, nb2);
        sa += a.x + a.y + a.z + a.w;
        sb += b.x + b.y + b.z + b.w;
    }
#pragma unroll
    for (int off = 16; off > 0; off >>= 1) {
        dot += __shfl_xor_sync(0xFFFFFFFFu, dot, off);
        na2 += __shfl_xor_sync(0xFFFFFFFFu, na2, off);
        nb2 += __shfl_xor_sync(0xFFFFFFFFu, nb2, off);
        sa  += __shfl_xor_sync(0xFFFFFFFFu, sa,  off);
        sb  += __shfl_xor_sync(0xFFFFFFFFu, sb,  off);
    }
    if (lane == 0) {
        float inva = rsqrtf(na2);
        float invb = rsqrtf(nb2);
        float d2 = 2.0f - 2.0f * dot * inva * invb
                 + 2.0f * EPS * (sa * inva - sb * invb)
                 + (float)D * EPS * EPS;
        d2 = fmaxf(d2, 0.0f);
        float v = 1.0f - sqrtf(d2);
        out[e] = 1.0f / (1.0f + __expf(-v));
    }
}

extern "C" void kernel_launch(void* const* d_in, const int* in_sizes, int n_in,
                              void* d_out, int out_size)
{
    const float* z = (const float*)d_in[0];
    const void* edge_index = d_in[1];
    float* out = (float*)d_out;

    int n_nodes = in_sizes[0] / D;
    int n_edges = in_sizes[1] / 2;

    detect_idx_dtype_kernel<<<1, 512>>>((const int*)edge_index);

    int warps_per_block = 256 / 32;
    int egrid = (n_edges + warps_per_block - 1) / warps_per_block;

    if (n_nodes <= NODE_CAP) {
        int ngrid = (n_nodes + warps_per_block - 1) / warps_per_block;
        prep_kernel<<<ngrid, 256>>>((const float4*)z, n_nodes);
        edge_decoder_h_kernel<<<egrid, 256>>>(edge_index, out, n_edges);
    } else {
        edge_decoder_f32_kernel<<<egrid, 256>>>(z, edge_index, out, n_edges);
    }
}

// round 5
// speedup vs baseline: 1.1591x; 1.1591x over previous
#include <cuda_runtime.h>
#include <stdint.h>

#define D 512               // embedding dim (fixed by problem)
#define EPS 1e-6f
#define NODE_CAP 50000      // capacity of the static int8 copy

// Runtime index-dtype flag: 1 if edge_index is int64, 0 if int32.
__device__ int g_idx_is64;

// int8 copy of z: one row = 512 bytes = 32 uint4. 25.6 MB (L2-resident).
__device__ uint4 g_q8[(size_t)NODE_CAP * 32];
// exact per-node 1/||row||, sum(row), and dequant scale (absmax/127), fp32
__device__ float g_inv[NODE_CAP];
__device__ float g_sum[NODE_CAP];
__device__ float g_scl[NODE_CAP];

// Standalone detect (only used on the fp32 fallback path)
__global__ void detect_idx_dtype_kernel(const int* __restrict__ raw)
{
    int lane = threadIdx.x & 31;
    int lo = raw[2 * lane];
    int hi = raw[2 * lane + 1];
    unsigned bad = __ballot_sync(0xFFFFFFFFu, hi != 0 || lo < 0);
    if (lane == 0) g_idx_is64 = (bad == 0) ? 1 : 0;
}

__device__ __forceinline__ unsigned pack4_q(float4 v, float k)
{
    int q0 = __float2int_rn(v.x * k);
    int q1 = __float2int_rn(v.y * k);
    int q2 = __float2int_rn(v.z * k);
    int q3 = __float2int_rn(v.w * k);
    return (q0 & 0xFF) | ((q1 & 0xFF) << 8) | ((q2 & 0xFF) << 16)
         | ((q3 & 0xFF) << 24);
}

// Pass 1: one warp per node. Stream z row (coalesced float4), compute exact
// fp32 norm/sum and absmax, quantize to int8, store one uint4 per lane.
// Warp 0 additionally performs index-dtype detection (runs before edge pass).
// Fixed per-row element permutation is fine: dot/norm/sum are invariant.
__global__ void __launch_bounds__(256)
prep_q8_kernel(const float4* __restrict__ z4,
               const int* __restrict__ raw_edges,
               int n_nodes)
{
    int warp = (blockIdx.x * blockDim.x + threadIdx.x) >> 5;
    int lane = threadIdx.x & 31;

    if (warp == 0) {
        // int64 little-endian indices in [0, n_nodes) => hi word always 0.
        // int32 => "hi" slot is another random index; P(all 32 zero) ~ 0.
        int lo = raw_edges[2 * lane];
        int hi = raw_edges[2 * lane + 1];
        unsigned bad = __ballot_sync(0xFFFFFFFFu, hi != 0 || lo < 0);
        if (lane == 0) g_idx_is64 = (bad == 0) ? 1 : 0;
    }
    if (warp >= n_nodes) return;

    const float4* __restrict__ R = z4 + (size_t)warp * (D / 4);
    float4 v[4];
#pragma unroll
    for (int j = 0; j < 4; j++) v[j] = R[lane + 32 * j];

    float na2 = 0.f, sa = 0.f, mx = 0.f;
#pragma unroll
    for (int j = 0; j < 4; j++) {
        float4 a = v[j];
        na2 = fmaf(a.x, a.x, na2); na2 = fmaf(a.y, a.y, na2);
        na2 = fmaf(a.z, a.z, na2); na2 = fmaf(a.w, a.w, na2);
        sa += a.x + a.y + a.z + a.w;
        mx = fmaxf(mx, fmaxf(fmaxf(fabsf(a.x), fabsf(a.y)),
                             fmaxf(fabsf(a.z), fabsf(a.w))));
    }

#pragma unroll
    for (int off = 16; off > 0; off >>= 1) {
        na2 += __shfl_xor_sync(0xFFFFFFFFu, na2, off);
        sa  += __shfl_xor_sync(0xFFFFFFFFu, sa,  off);
        mx  = fmaxf(mx, __shfl_xor_sync(0xFFFFFFFFu, mx, off));
    }

    mx = fmaxf(mx, 1e-20f);
    float k = 127.0f / mx;   // quantize multiplier (uniform across warp)

    uint4 q;
    q.x = pack4_q(v[0], k);
    q.y = pack4_q(v[1], k);
    q.z = pack4_q(v[2], k);
    q.w = pack4_q(v[3], k);
    g_q8[(size_t)warp * 32 + lane] = q;

    if (lane == 0) {
        g_inv[warp] = rsqrtf(na2);
        g_sum[warp] = sa;
        g_scl[warp] = mx * (1.0f / 127.0f);
    }
}

// Pass 2: one warp per edge. Gather two int8 rows (512 B each = 1 uint4 per
// lane), exact integer dot via dp4a, dequantize with per-row scales.
//   dist^2 = 2 - 2*dot*inva*invb + 2*eps*(sa*inva - sb*invb) + D*eps^2
//   out    = sigmoid(1 - sqrt(max(dist^2, 0)))
__global__ void __launch_bounds__(256)
edge_decoder_q8_kernel(const void* __restrict__ edge_index,
                       float* __restrict__ out,
                       int n_edges)
{
    int e = (blockIdx.x * blockDim.x + threadIdx.x) >> 5;
    int lane = threadIdx.x & 31;
    if (e >= n_edges) return;

    long long ia, ib;
    if (g_idx_is64) {
        const long long* ei = (const long long*)edge_index;
        ia = ei[e];
        ib = ei[e + n_edges];
    } else {
        const int* ei = (const int*)edge_index;
        ia = ei[e];
        ib = ei[e + n_edges];
    }

    const uint4* __restrict__ A = g_q8 + ia * 32;
    const uint4* __restrict__ B = g_q8 + ib * 32;

    uint4 qa = A[lane];
    uint4 qb = B[lane];

    int idot = __dp4a((int)qa.x, (int)qb.x, 0);
    idot = __dp4a((int)qa.y, (int)qb.y, idot);
    idot = __dp4a((int)qa.z, (int)qb.z, idot);
    idot = __dp4a((int)qa.w, (int)qb.w, idot);

#pragma unroll
    for (int off = 16; off > 0; off >>= 1)
        idot += __shfl_xor_sync(0xFFFFFFFFu, idot, off);

    if (lane == 0) {
        float dot  = (float)idot * g_scl[ia] * g_scl[ib];
        float inva = g_inv[ia];
        float invb = g_inv[ib];
        float sa   = g_sum[ia];
        float sb   = g_sum[ib];
        float d2 = 2.0f - 2.0f * dot * inva * invb
                 + 2.0f * EPS * (sa * inva - sb * invb)
                 + (float)D * EPS * EPS;
        d2 = fmaxf(d2, 0.0f);
        float v = 1.0f - sqrtf(d2);
        out[e] = 1.0f / (1.0f + __expf(-v));
    }
}

// Fallback (fp32 fused, one warp per edge) if n_nodes exceeds static capacity.
__global__ void __launch_bounds__(256)
edge_decoder_f32_kernel(const float* __restrict__ z,
                        const void* __restrict__ edge_index,
                        float* __restrict__ out,
                        int n_edges)
{
    int e = (blockIdx.x * blockDim.x + threadIdx.x) >> 5;
    int lane = threadIdx.x & 31;
    if (e >= n_edges) return;

    long long ia, ib;
    if (g_idx_is64) {
        const long long* ei = (const long long*)edge_index;
        ia = ei[e];
        ib = ei[e + n_edges];
    } else {
        const int* ei = (const int*)edge_index;
        ia = ei[e];
        ib = ei[e + n_edges];
    }

    const float4* A = reinterpret_cast<const float4*>(z + ia * (long long)D);
    const float4* B = reinterpret_cast<const float4*>(z + ib * (long long)D);

    float dot = 0.f, na2 = 0.f, nb2 = 0.f, sa = 0.f, sb = 0.f;
    float4 av[4], bv[4];
#pragma unroll
    for (int j = 0; j < 4; j++) {
        av[j] = A[lane + 32 * j];
        bv[j] = B[lane + 32 * j];
    }
#pragma unroll
    for (int j = 0; j < 4; j++) {
        float4 a = av[j], b = bv[j];
        dot = fmaf(a.x, b.x, dot); dot = fmaf(a.y, b.y, dot);
        dot = fmaf(a.z, b.z, dot); dot = fmaf(a.w, b.w, dot);
        na2 = fmaf(a.x, a.x, na2); na2 = fmaf(a.y, a.y, na2);
        na2 = fmaf(a.z, a.z, na2); na2 = fmaf(a.w, a.w, na2);
        nb2 = fmaf(b.x, b.x, nb2); nb2 = fmaf(b.y, b.y, nb2);
        nb2 = fmaf(b.z, b.z, nb2); nb2 = fmaf(b.w, b.w, nb2);
        sa += a.x + a.y + a.z + a.w;
        sb += b.x + b.y + b.z + b.w;
    }
#pragma unroll
    for (int off = 16; off > 0; off >>= 1) {
        dot += __shfl_xor_sync(0xFFFFFFFFu, dot, off);
        na2 += __shfl_xor_sync(0xFFFFFFFFu, na2, off);
        nb2 += __shfl_xor_sync(0xFFFFFFFFu, nb2, off);
        sa  += __shfl_xor_sync(0xFFFFFFFFu, sa,  off);
        sb  += __shfl_xor_sync(0xFFFFFFFFu, sb,  off);
    }
    if (lane == 0) {
        float inva = rsqrtf(na2);
        float invb = rsqrtf(nb2);
        float d2 = 2.0f - 2.0f * dot * inva * invb
                 + 2.0f * EPS * (sa * inva - sb * invb)
                 + (float)D * EPS * EPS;
        d2 = fmaxf(d2, 0.0f);
        float v = 1.0f - sqrtf(d2);
        out[e] = 1.0f / (1.0f + __expf(-v));
    }
}

extern "C" void kernel_launch(void* const* d_in, const int* in_sizes, int n_in,
                              void* d_out, int out_size)
{
    const float* z = (const float*)d_in[0];
    const void* edge_index = d_in[1];
    float* out = (float*)d_out;

    int n_nodes = in_sizes[0] / D;
    int n_edges = in_sizes[1] / 2;

    int warps_per_block = 256 / 32;
    int egrid = (n_edges + warps_per_block - 1) / warps_per_block;

    if (n_nodes <= NODE_CAP) {
        int ngrid = (n_nodes + warps_per_block - 1) / warps_per_block;
        prep_q8_kernel<<<ngrid, 256>>>((const float4*)z,
                                       (const int*)edge_index, n_nodes);
        edge_decoder_q8_kernel<<<egrid, 256>>>(edge_index, out, n_edges);
    } else {
        detect_idx_dtype_kernel<<<1, 32>>>((const int*)edge_index);
        edge_decoder_f32_kernel<<<egrid, 256>>>(z, edge_index, out, n_edges);
    }
}

// round 6
// speedup vs baseline: 1.3297x; 1.1472x over previous
#include <cuda_runtime.h>
#include <stdint.h>

#define D 512               // embedding dim (fixed by problem)
#define EPS 1e-6f
#define NODE_CAP 50000      // capacity of the static int8 copy

// Runtime index-dtype flag: 1 if edge_index is int64, 0 if int32.
__device__ int g_idx_is64;

// int8 copy of z: one row = 512 bytes = 32 uint4. 25.6 MB (L2-resident).
__device__ uint4 g_q8[(size_t)NODE_CAP * 32];
// combined per-node constants: c.x = (absmax/127)*inv_norm, c.y = sum*inv_norm
__device__ float2 g_c[NODE_CAP];

// Standalone detect (only used on the fp32 fallback path)
__global__ void detect_idx_dtype_kernel(const int* __restrict__ raw)
{
    int lane = threadIdx.x & 31;
    int lo = raw[2 * lane];
    int hi = raw[2 * lane + 1];
    unsigned bad = __ballot_sync(0xFFFFFFFFu, hi != 0 || lo < 0);
    if (lane == 0) g_idx_is64 = (bad == 0) ? 1 : 0;
}

__device__ __forceinline__ unsigned pack4_q(float4 v, float k)
{
    int q0 = __float2int_rn(v.x * k);
    int q1 = __float2int_rn(v.y * k);
    int q2 = __float2int_rn(v.z * k);
    int q3 = __float2int_rn(v.w * k);
    return (q0 & 0xFF) | ((q1 & 0xFF) << 8) | ((q2 & 0xFF) << 16)
         | ((q3 & 0xFF) << 24);
}

// Pass 1: one warp per node. Stream z row (coalesced float4), compute exact
// fp32 norm/sum and absmax, quantize to int8, store one uint4 per lane.
// Warp 0 additionally performs index-dtype detection.
__global__ void __launch_bounds__(256)
prep_q8_kernel(const float4* __restrict__ z4,
               const int* __restrict__ raw_edges,
               int n_nodes)
{
    int warp = (blockIdx.x * blockDim.x + threadIdx.x) >> 5;
    int lane = threadIdx.x & 31;

    if (warp == 0) {
        // int64 little-endian indices in [0, n_nodes) => hi word always 0.
        int lo = raw_edges[2 * lane];
        int hi = raw_edges[2 * lane + 1];
        unsigned bad = __ballot_sync(0xFFFFFFFFu, hi != 0 || lo < 0);
        if (lane == 0) g_idx_is64 = (bad == 0) ? 1 : 0;
    }
    if (warp >= n_nodes) return;

    const float4* __restrict__ R = z4 + (size_t)warp * (D / 4);
    float4 v[4];
#pragma unroll
    for (int j = 0; j < 4; j++) v[j] = R[lane + 32 * j];

    float na2 = 0.f, sa = 0.f, mx = 0.f;
#pragma unroll
    for (int j = 0; j < 4; j++) {
        float4 a = v[j];
        na2 = fmaf(a.x, a.x, na2); na2 = fmaf(a.y, a.y, na2);
        na2 = fmaf(a.z, a.z, na2); na2 = fmaf(a.w, a.w, na2);
        sa += a.x + a.y + a.z + a.w;
        mx = fmaxf(mx, fmaxf(fmaxf(fabsf(a.x), fabsf(a.y)),
                             fmaxf(fabsf(a.z), fabsf(a.w))));
    }

#pragma unroll
    for (int off = 16; off > 0; off >>= 1) {
        na2 += __shfl_xor_sync(0xFFFFFFFFu, na2, off);
        sa  += __shfl_xor_sync(0xFFFFFFFFu, sa,  off);
        mx  = fmaxf(mx, __shfl_xor_sync(0xFFFFFFFFu, mx, off));
    }

    mx = fmaxf(mx, 1e-20f);
    float k = 127.0f / mx;

    uint4 q;
    q.x = pack4_q(v[0], k);
    q.y = pack4_q(v[1], k);
    q.z = pack4_q(v[2], k);
    q.w = pack4_q(v[3], k);
    g_q8[(size_t)warp * 32 + lane] = q;

    if (lane == 0) {
        float inv = rsqrtf(na2);
        float2 c;
        c.x = mx * (1.0f / 127.0f) * inv;   // dequant * inv_norm (for dot)
        c.y = sa * inv;                     // sum * inv_norm     (for eps term)
        g_c[warp] = c;
    }
}

// Pass 2: one warp per FOUR edges. Per lane: 8 independent uint4 gathers in
// flight (4 edges x 2 endpoints), dp4a integer dots, REDUX.SUM reduction,
// then lanes 0-3 run the 4 scalar epilogues in parallel.
//   dist^2 = 2 - 2*dot_n + 2*eps*(c2a - c2b) + D*eps^2,  dot_n = idot*c1a*c1b
//   out    = sigmoid(1 - sqrt(max(dist^2, 0)))
__global__ void __launch_bounds__(256)
edge_decoder_q8x4_kernel(const void* __restrict__ edge_index,
                         float* __restrict__ out,
                         int n_edges)
{
    int grp  = (blockIdx.x * blockDim.x + threadIdx.x) >> 5;
    int lane = threadIdx.x & 31;
    int e0 = grp * 4;
    if (e0 >= n_edges) return;

    // Load 8 indices (broadcast loads: all lanes same address -> 1 wavefront).
    long long ia[4], ib[4];
    if (g_idx_is64) {
        const long long* ei = (const long long*)edge_index;
#pragma unroll
        for (int j = 0; j < 4; j++) {
            int e = min(e0 + j, n_edges - 1);
            ia[j] = ei[e];
            ib[j] = ei[e + n_edges];
        }
    } else {
        const int* ei = (const int*)edge_index;
#pragma unroll
        for (int j = 0; j < 4; j++) {
            int e = min(e0 + j, n_edges - 1);
            ia[j] = ei[e];
            ib[j] = ei[e + n_edges];
        }
    }

    // 8 independent gathers per lane.
    uint4 qa[4], qb[4];
#pragma unroll
    for (int j = 0; j < 4; j++) qa[j] = g_q8[ia[j] * 32 + lane];
#pragma unroll
    for (int j = 0; j < 4; j++) qb[j] = g_q8[ib[j] * 32 + lane];

    int idot[4];
#pragma unroll
    for (int j = 0; j < 4; j++) {
        int t = __dp4a((int)qa[j].x, (int)qb[j].x, 0);
        t = __dp4a((int)qa[j].y, (int)qb[j].y, t);
        t = __dp4a((int)qa[j].z, (int)qb[j].z, t);
        t = __dp4a((int)qa[j].w, (int)qb[j].w, t);
        idot[j] = t;
    }

    // Single-instruction warp reductions (REDUX.SUM), result in all lanes.
#pragma unroll
    for (int j = 0; j < 4; j++)
        idot[j] = __reduce_add_sync(0xFFFFFFFFu, idot[j]);

    // Lanes 0-3 handle one edge each, in parallel.
    if (lane < 4 && e0 + lane < n_edges) {
        int mydot = idot[0];
        if (lane == 1) mydot = idot[1];
        if (lane == 2) mydot = idot[2];
        if (lane == 3) mydot = idot[3];
        long long mia = ia[lane];
        long long mib = ib[lane];

        float2 ca = g_c[mia];
        float2 cb = g_c[mib];
        float dot_n = (float)mydot * ca.x * cb.x;
        float d2 = 2.0f - 2.0f * dot_n
                 + 2.0f * EPS * (ca.y - cb.y)
                 + (float)D * EPS * EPS;
        d2 = fmaxf(d2, 0.0f);
        float v = 1.0f - sqrtf(d2);
        out[e0 + lane] = 1.0f / (1.0f + __expf(-v));
    }
}

// Fallback (fp32 fused, one warp per edge) if n_nodes exceeds static capacity.
__global__ void __launch_bounds__(256)
edge_decoder_f32_kernel(const float* __restrict__ z,
                        const void* __restrict__ edge_index,
                        float* __restrict__ out,
                        int n_edges)
{
    int e = (blockIdx.x * blockDim.x + threadIdx.x) >> 5;
    int lane = threadIdx.x & 31;
    if (e >= n_edges) return;

    long long ia, ib;
    if (g_idx_is64) {
        const long long* ei = (const long long*)edge_index;
        ia = ei[e];
        ib = ei[e + n_edges];
    } else {
        const int* ei = (const int*)edge_index;
        ia = ei[e];
        ib = ei[e + n_edges];
    }

    const float4* A = reinterpret_cast<const float4*>(z + ia * (long long)D);
    const float4* B = reinterpret_cast<const float4*>(z + ib * (long long)D);

    float dot = 0.f, na2 = 0.f, nb2 = 0.f, sa = 0.f, sb = 0.f;
    float4 av[4], bv[4];
#pragma unroll
    for (int j = 0; j < 4; j++) {
        av[j] = A[lane + 32 * j];
        bv[j] = B[lane + 32 * j];
    }
#pragma unroll
    for (int j = 0; j < 4; j++) {
        float4 a = av[j], b = bv[j];
        dot = fmaf(a.x, b.x, dot); dot = fmaf(a.y, b.y, dot);
        dot = fmaf(a.z, b.z, dot); dot = fmaf(a.w, b.w, dot);
        na2 = fmaf(a.x, a.x, na2); na2 = fmaf(a.y, a.y, na2);
        na2 = fmaf(a.z, a.z, na2); na2 = fmaf(a.w, a.w, na2);
        nb2 = fmaf(b.x, b.x, nb2); nb2 = fmaf(b.y, b.y, nb2);
        nb2 = fmaf(b.z, b.z, nb2); nb2 = fmaf(b.w, b.w, nb2);
        sa += a.x + a.y + a.z + a.w;
        sb += b.x + b.y + b.z + b.w;
    }
#pragma unroll
    for (int off = 16; off > 0; off >>= 1) {
        dot += __shfl_xor_sync(0xFFFFFFFFu, dot, off);
        na2 += __shfl_xor_sync(0xFFFFFFFFu, na2, off);
        nb2 += __shfl_xor_sync(0xFFFFFFFFu, nb2, off);
        sa  += __shfl_xor_sync(0xFFFFFFFFu, sa,  off);
        sb  += __shfl_xor_sync(0xFFFFFFFFu, sb,  off);
    }
    if (lane == 0) {
        float inva = rsqrtf(na2);
        float invb = rsqrtf(nb2);
        float d2 = 2.0f - 2.0f * dot * inva * invb
                 + 2.0f * EPS * (sa * inva - sb * invb)
                 + (float)D * EPS * EPS;
        d2 = fmaxf(d2, 0.0f);
        float v = 1.0f - sqrtf(d2);
        out[e] = 1.0f / (1.0f + __expf(-v));
    }
}

extern "C" void kernel_launch(void* const* d_in, const int* in_sizes, int n_in,
                              void* d_out, int out_size)
{
    const float* z = (const float*)d_in[0];
    const void* edge_index = d_in[1];
    float* out = (float*)d_out;

    int n_nodes = in_sizes[0] / D;
    int n_edges = in_sizes[1] / 2;

    if (n_nodes <= NODE_CAP) {
        int ngrid = (n_nodes + 7) / 8;                 // 8 warps/block
        prep_q8_kernel<<<ngrid, 256>>>((const float4*)z,
                                       (const int*)edge_index, n_nodes);
        int ngroups = (n_edges + 3) / 4;               // 4 edges per warp
        int egrid = (ngroups + 7) / 8;                 // 8 warps/block
        edge_decoder_q8x4_kernel<<<egrid, 256>>>(edge_index, out, n_edges);
    } else {
        detect_idx_dtype_kernel<<<1, 32>>>((const int*)edge_index);
        int egrid = (n_edges + 7) / 8;
        edge_decoder_f32_kernel<<<egrid, 256>>>(z, edge_index, out, n_edges);
    }
}

// round 7
// speedup vs baseline: 1.5379x; 1.1566x over previous
#include <cuda_runtime.h>
#include <stdint.h>

#define D 512               // embedding dim (fixed by problem)
#define EPS 1e-6f
#define NODE_CAP 50000      // capacity of the static int8 copy

// Runtime index-dtype flag: 1 if edge_index is int64, 0 if int32.
__device__ int g_idx_is64;

// int8 copy of z: one row = 512 bytes = 32 uint4. 25.6 MB (L2-resident).
__device__ uint4 g_q8[(size_t)NODE_CAP * 32];
// combined per-node constants: c.x = (absmax/127)*inv_norm, c.y = sum*inv_norm
__device__ float2 g_c[NODE_CAP];

// Standalone detect (only used on the fp32 fallback path)
__global__ void detect_idx_dtype_kernel(const int* __restrict__ raw)
{
    int lane = threadIdx.x & 31;
    int lo = raw[2 * lane];
    int hi = raw[2 * lane + 1];
    unsigned bad = __ballot_sync(0xFFFFFFFFu, hi != 0 || lo < 0);
    if (lane == 0) g_idx_is64 = (bad == 0) ? 1 : 0;
}

__device__ __forceinline__ unsigned pack4_q(float4 v, float k)
{
    int q0 = __float2int_rn(v.x * k);
    int q1 = __float2int_rn(v.y * k);
    int q2 = __float2int_rn(v.z * k);
    int q3 = __float2int_rn(v.w * k);
    return (q0 & 0xFF) | ((q1 & 0xFF) << 8) | ((q2 & 0xFF) << 16)
         | ((q3 & 0xFF) << 24);
}

// Pass 1: one warp per node. Stream z row with __ldcs (evict-first: do NOT
// let the 100MB z stream evict the q8 table we are writing into L2),
// compute exact fp32 norm/sum and absmax, quantize to int8.
// Warp 0 additionally performs index-dtype detection.
__global__ void __launch_bounds__(256)
prep_q8_kernel(const float4* __restrict__ z4,
               const int* __restrict__ raw_edges,
               int n_nodes)
{
    int warp = (blockIdx.x * blockDim.x + threadIdx.x) >> 5;
    int lane = threadIdx.x & 31;

    if (warp == 0) {
        // int64 little-endian indices in [0, n_nodes) => hi word always 0.
        int lo = raw_edges[2 * lane];
        int hi = raw_edges[2 * lane + 1];
        unsigned bad = __ballot_sync(0xFFFFFFFFu, hi != 0 || lo < 0);
        if (lane == 0) g_idx_is64 = (bad == 0) ? 1 : 0;
    }
    if (warp >= n_nodes) return;

    const float4* __restrict__ R = z4 + (size_t)warp * (D / 4);
    float4 v[4];
#pragma unroll
    for (int j = 0; j < 4; j++) v[j] = __ldcs(&R[lane + 32 * j]);

    float na2 = 0.f, sa = 0.f, mx = 0.f;
#pragma unroll
    for (int j = 0; j < 4; j++) {
        float4 a = v[j];
        na2 = fmaf(a.x, a.x, na2); na2 = fmaf(a.y, a.y, na2);
        na2 = fmaf(a.z, a.z, na2); na2 = fmaf(a.w, a.w, na2);
        sa += a.x + a.y + a.z + a.w;
        mx = fmaxf(mx, fmaxf(fmaxf(fabsf(a.x), fabsf(a.y)),
                             fmaxf(fabsf(a.z), fabsf(a.w))));
    }

#pragma unroll
    for (int off = 16; off > 0; off >>= 1) {
        na2 += __shfl_xor_sync(0xFFFFFFFFu, na2, off);
        sa  += __shfl_xor_sync(0xFFFFFFFFu, sa,  off);
        mx  = fmaxf(mx, __shfl_xor_sync(0xFFFFFFFFu, mx, off));
    }

    mx = fmaxf(mx, 1e-20f);
    float k = 127.0f / mx;

    uint4 q;
    q.x = pack4_q(v[0], k);
    q.y = pack4_q(v[1], k);
    q.z = pack4_q(v[2], k);
    q.w = pack4_q(v[3], k);
    g_q8[(size_t)warp * 32 + lane] = q;

    if (lane == 0) {
        float inv = rsqrtf(na2);
        float2 c;
        c.x = mx * (1.0f / 127.0f) * inv;   // dequant * inv_norm (for dot)
        c.y = sa * inv;                     // sum * inv_norm     (for eps term)
        g_c[warp] = c;
    }
}

// Pass 2: one warp per EIGHT edges. Per lane: 16 independent uint4 gathers in
// flight, dp4a integer dots, REDUX.SUM reductions, then lanes 0-7 run the 8
// scalar epilogues in parallel.
//   dist^2 = 2 - 2*dot_n + 2*eps*(c2a - c2b) + D*eps^2,  dot_n = idot*c1a*c1b
//   out    = sigmoid(1 - sqrt(max(dist^2, 0)))
__global__ void __launch_bounds__(256, 2)
edge_decoder_q8x8_kernel(const void* __restrict__ edge_index,
                         float* __restrict__ out,
                         int n_edges)
{
    int grp  = (blockIdx.x * blockDim.x + threadIdx.x) >> 5;
    int lane = threadIdx.x & 31;
    int e0 = grp * 8;
    if (e0 >= n_edges) return;

    bool full = (e0 + 8 <= n_edges);

    // Load 16 indices; vectorized broadcast loads when in-bounds.
    long long ia[8], ib[8];
    if (g_idx_is64) {
        const long long* ei = (const long long*)edge_index;
        if (full) {
            const longlong2* pa = (const longlong2*)(ei + e0);
            const longlong2* pb = (const longlong2*)(ei + e0 + n_edges);
#pragma unroll
            for (int j = 0; j < 4; j++) {
                longlong2 t = pa[j]; ia[2*j] = t.x; ia[2*j+1] = t.y;
                longlong2 u = pb[j]; ib[2*j] = u.x; ib[2*j+1] = u.y;
            }
        } else {
#pragma unroll
            for (int j = 0; j < 8; j++) {
                int e = min(e0 + j, n_edges - 1);
                ia[j] = ei[e];
                ib[j] = ei[e + n_edges];
            }
        }
    } else {
        const int* ei = (const int*)edge_index;
        if (full && (((uintptr_t)(ei + e0) & 15) == 0)
                 && (((uintptr_t)(ei + e0 + n_edges) & 15) == 0)) {
            const int4* pa = (const int4*)(ei + e0);
            const int4* pb = (const int4*)(ei + e0 + n_edges);
#pragma unroll
            for (int j = 0; j < 2; j++) {
                int4 t = pa[j];
                ia[4*j] = t.x; ia[4*j+1] = t.y; ia[4*j+2] = t.z; ia[4*j+3] = t.w;
                int4 u = pb[j];
                ib[4*j] = u.x; ib[4*j+1] = u.y; ib[4*j+2] = u.z; ib[4*j+3] = u.w;
            }
        } else {
#pragma unroll
            for (int j = 0; j < 8; j++) {
                int e = min(e0 + j, n_edges - 1);
                ia[j] = ei[e];
                ib[j] = ei[e + n_edges];
            }
        }
    }

    // 16 independent gathers per lane (front-batched for MLP).
    uint4 qa[8], qb[8];
#pragma unroll
    for (int j = 0; j < 8; j++) qa[j] = g_q8[ia[j] * 32 + lane];
#pragma unroll
    for (int j = 0; j < 8; j++) qb[j] = g_q8[ib[j] * 32 + lane];

    int idot[8];
#pragma unroll
    for (int j = 0; j < 8; j++) {
        int t = __dp4a((int)qa[j].x, (int)qb[j].x, 0);
        t = __dp4a((int)qa[j].y, (int)qb[j].y, t);
        t = __dp4a((int)qa[j].z, (int)qb[j].z, t);
        t = __dp4a((int)qa[j].w, (int)qb[j].w, t);
        idot[j] = t;
    }

    // Single-instruction warp reductions (REDUX.SUM), result in all lanes.
#pragma unroll
    for (int j = 0; j < 8; j++)
        idot[j] = __reduce_add_sync(0xFFFFFFFFu, idot[j]);

    // Lanes 0-7 handle one edge each, in parallel.
    if (lane < 8 && e0 + lane < n_edges) {
        int mydot = idot[0];
#pragma unroll
        for (int j = 1; j < 8; j++) if (lane == j) mydot = idot[j];

        long long mia = ia[0], mib = ib[0];
#pragma unroll
        for (int j = 1; j < 8; j++) {
            if (lane == j) { mia = ia[j]; mib = ib[j]; }
        }

        float2 ca = g_c[mia];
        float2 cb = g_c[mib];
        float dot_n = (float)mydot * ca.x * cb.x;
        float d2 = 2.0f - 2.0f * dot_n
                 + 2.0f * EPS * (ca.y - cb.y)
                 + (float)D * EPS * EPS;
        d2 = fmaxf(d2, 0.0f);
        float v = 1.0f - sqrtf(d2);
        out[e0 + lane] = 1.0f / (1.0f + __expf(-v));
    }
}

// Fallback (fp32 fused, one warp per edge) if n_nodes exceeds static capacity.
__global__ void __launch_bounds__(256)
edge_decoder_f32_kernel(const float* __restrict__ z,
                        const void* __restrict__ edge_index,
                        float* __restrict__ out,
                        int n_edges)
{
    int e = (blockIdx.x * blockDim.x + threadIdx.x) >> 5;
    int lane = threadIdx.x & 31;
    if (e >= n_edges) return;

    long long ia, ib;
    if (g_idx_is64) {
        const long long* ei = (const long long*)edge_index;
        ia = ei[e];
        ib = ei[e + n_edges];
    } else {
        const int* ei = (const int*)edge_index;
        ia = ei[e];
        ib = ei[e + n_edges];
    }

    const float4* A = reinterpret_cast<const float4*>(z + ia * (long long)D);
    const float4* B = reinterpret_cast<const float4*>(z + ib * (long long)D);

    float dot = 0.f, na2 = 0.f, nb2 = 0.f, sa = 0.f, sb = 0.f;
    float4 av[4], bv[4];
#pragma unroll
    for (int j = 0; j < 4; j++) {
        av[j] = A[lane + 32 * j];
        bv[j] = B[lane + 32 * j];
    }
#pragma unroll
    for (int j = 0; j < 4; j++) {
        float4 a = av[j], b = bv[j];
        dot = fmaf(a.x, b.x, dot); dot = fmaf(a.y, b.y, dot);
        dot = fmaf(a.z, b.z, dot); dot = fmaf(a.w, b.w, dot);
        na2 = fmaf(a.x, a.x, na2); na2 = fmaf(a.y, a.y, na2);
        na2 = fmaf(a.z, a.z, na2); na2 = fmaf(a.w, a.w, na2);
        nb2 = fmaf(b.x, b.x, nb2); nb2 = fmaf(b.y, b.y, nb2);
        nb2 = fmaf(b.z, b.z, nb2); nb2 = fmaf(b.w, b.w, nb2);
        sa += a.x + a.y + a.z + a.w;
        sb += b.x + b.y + b.z + b.w;
    }
#pragma unroll
    for (int off = 16; off > 0; off >>= 1) {
        dot += __shfl_xor_sync(0xFFFFFFFFu, dot, off);
        na2 += __shfl_xor_sync(0xFFFFFFFFu, na2, off);
        nb2 += __shfl_xor_sync(0xFFFFFFFFu, nb2, off);
        sa  += __shfl_xor_sync(0xFFFFFFFFu, sa,  off);
        sb  += __shfl_xor_sync(0xFFFFFFFFu, sb,  off);
    }
    if (lane == 0) {
        float inva = rsqrtf(na2);
        float invb = rsqrtf(nb2);
        float d2 = 2.0f - 2.0f * dot * inva * invb
                 + 2.0f * EPS * (sa * inva - sb * invb)
                 + (float)D * EPS * EPS;
        d2 = fmaxf(d2, 0.0f);
        float v = 1.0f - sqrtf(d2);
        out[e] = 1.0f / (1.0f + __expf(-v));
    }
}

extern "C" void kernel_launch(void* const* d_in, const int* in_sizes, int n_in,
                              void* d_out, int out_size)
{
    const float* z = (const float*)d_in[0];
    const void* edge_index = d_in[1];
    float* out = (float*)d_out;

    int n_nodes = in_sizes[0] / D;
    int n_edges = in_sizes[1] / 2;

    if (n_nodes <= NODE_CAP) {
        int ngrid = (n_nodes + 7) / 8;                 // 8 warps/block
        prep_q8_kernel<<<ngrid, 256>>>((const float4*)z,
                                       (const int*)edge_index, n_nodes);
        int ngroups = (n_edges + 7) / 8;               // 8 edges per warp
        int egrid = (ngroups + 7) / 8;                 // 8 warps/block
        edge_decoder_q8x8_kernel<<<egrid, 256>>>(edge_index, out, n_edges);
    } else {
        detect_idx_dtype_kernel<<<1, 32>>>((const int*)edge_index);
        int egrid = (n_edges + 7) / 8;
        edge_decoder_f32_kernel<<<egrid, 256>>>(z, edge_index, out, n_edges);
    }
}

// round 8
// speedup vs baseline: 1.6457x; 1.0701x over previous
#include <cuda_runtime.h>
#include <stdint.h>

#define D 512               // embedding dim (fixed by problem)
#define EPS 1e-6f
#define NODE_CAP 50000      // capacity of the static int8 copy

// Runtime index-dtype flag: 1 if edge_index is int64, 0 if int32.
__device__ int g_idx_is64;

// int8 copy of z: one row = 512 bytes. 25.6 MB (mostly L2-resident).
__device__ __align__(16) unsigned char g_q8[(size_t)NODE_CAP * 512];
// combined per-node constants: c.x = (absmax/127)*inv_norm, c.y = sum*inv_norm
__device__ float2 g_c[NODE_CAP];

// Standalone detect (only used on the fp32 fallback path)
__global__ void detect_idx_dtype_kernel(const int* __restrict__ raw)
{
    int lane = threadIdx.x & 31;
    int lo = raw[2 * lane];
    int hi = raw[2 * lane + 1];
    unsigned bad = __ballot_sync(0xFFFFFFFFu, hi != 0 || lo < 0);
    if (lane == 0) g_idx_is64 = (bad == 0) ? 1 : 0;
}

__device__ __forceinline__ unsigned pack4_q(float4 v, float k)
{
    int q0 = __float2int_rn(v.x * k);
    int q1 = __float2int_rn(v.y * k);
    int q2 = __float2int_rn(v.z * k);
    int q3 = __float2int_rn(v.w * k);
    return (q0 & 0xFF) | ((q1 & 0xFF) << 8) | ((q2 & 0xFF) << 16)
         | ((q3 & 0xFF) << 24);
}

// Pass 1: one warp per node. Stream z row with __ldcs (evict-first),
// compute exact fp32 norm/sum and absmax, quantize to int8.
// Warp 0 additionally performs index-dtype detection.
__global__ void __launch_bounds__(256)
prep_q8_kernel(const float4* __restrict__ z4,
               const int* __restrict__ raw_edges,
               int n_nodes)
{
    int warp = (blockIdx.x * blockDim.x + threadIdx.x) >> 5;
    int lane = threadIdx.x & 31;

    if (warp == 0) {
        // int64 little-endian indices in [0, n_nodes) => hi word always 0.
        int lo = raw_edges[2 * lane];
        int hi = raw_edges[2 * lane + 1];
        unsigned bad = __ballot_sync(0xFFFFFFFFu, hi != 0 || lo < 0);
        if (lane == 0) g_idx_is64 = (bad == 0) ? 1 : 0;
    }
    if (warp >= n_nodes) return;

    const float4* __restrict__ R = z4 + (size_t)warp * (D / 4);
    float4 v[4];
#pragma unroll
    for (int j = 0; j < 4; j++) v[j] = __ldcs(&R[lane + 32 * j]);

    float na2 = 0.f, sa = 0.f, mx = 0.f;
#pragma unroll
    for (int j = 0; j < 4; j++) {
        float4 a = v[j];
        na2 = fmaf(a.x, a.x, na2); na2 = fmaf(a.y, a.y, na2);
        na2 = fmaf(a.z, a.z, na2); na2 = fmaf(a.w, a.w, na2);
        sa += a.x + a.y + a.z + a.w;
        mx = fmaxf(mx, fmaxf(fmaxf(fabsf(a.x), fabsf(a.y)),
                             fmaxf(fabsf(a.z), fabsf(a.w))));
    }

#pragma unroll
    for (int off = 16; off > 0; off >>= 1) {
        na2 += __shfl_xor_sync(0xFFFFFFFFu, na2, off);
        sa  += __shfl_xor_sync(0xFFFFFFFFu, sa,  off);
        mx  = fmaxf(mx, __shfl_xor_sync(0xFFFFFFFFu, mx, off));
    }

    mx = fmaxf(mx, 1e-20f);
    float k = 127.0f / mx;

    uint4 q;
    q.x = pack4_q(v[0], k);
    q.y = pack4_q(v[1], k);
    q.z = pack4_q(v[2], k);
    q.w = pack4_q(v[3], k);
    reinterpret_cast<uint4*>(g_q8)[(size_t)warp * 32 + lane] = q;

    if (lane == 0) {
        float inv = rsqrtf(na2);
        float2 c;
        c.x = mx * (1.0f / 127.0f) * inv;   // dequant * inv_norm (for dot)
        c.y = sa * inv;                     // sum * inv_norm     (for eps term)
        g_c[warp] = c;
    }
}

// Pass 2: one warp per EIGHT edges, cp.async staging through shared memory.
// Per lane: 16 LDGSTS (16B each) in flight — MLP decoupled from registers,
// so occupancy stays high. Then LDS.128 + dp4a + REDUX.SUM per edge; lanes
// 0-7 run the 8 scalar epilogues in parallel.
//   dist^2 = 2 - 2*dot_n + 2*eps*(c2a - c2b) + D*eps^2,  dot_n = idot*c1a*c1b
//   out    = sigmoid(1 - sqrt(max(dist^2, 0)))
__global__ void __launch_bounds__(128)
edge_decoder_cpasync_kernel(const void* __restrict__ edge_index,
                            float* __restrict__ out,
                            int n_edges)
{
    // 4 warps/block * 16 rows * 512 B = 32 KB
    __shared__ __align__(16) unsigned char sbuf[4][16 * 512];

    int wslot = threadIdx.x >> 5;
    int lane  = threadIdx.x & 31;
    int grp   = (blockIdx.x * blockDim.x + threadIdx.x) >> 5;
    int e0 = grp * 8;
    if (e0 >= n_edges) return;

    // Gather 16 node indices (int32; node ids < 50K). Broadcast loads.
    int idx[16];             // [0..7] = a-side, [8..15] = b-side
    if (g_idx_is64) {
        const long long* ei = (const long long*)edge_index;
#pragma unroll
        for (int j = 0; j < 8; j++) {
            int e = min(e0 + j, n_edges - 1);
            idx[j]     = (int)ei[e];
            idx[8 + j] = (int)ei[e + n_edges];
        }
    } else {
        const int* ei = (const int*)edge_index;
#pragma unroll
        for (int j = 0; j < 8; j++) {
            int e = min(e0 + j, n_edges - 1);
            idx[j]     = ei[e];
            idx[8 + j] = ei[e + n_edges];
        }
    }

    // Stage 16 rows into smem: each lane issues 16 independent 16B cp.asyncs.
    unsigned sbase;
    {
        void* p = &sbuf[wslot][0];
        asm("{ .reg .u64 t; cvta.to.shared.u64 t, %1; cvt.u32.u64 %0, t; }"
            : "=r"(sbase) : "l"(p));
    }
    const unsigned char* gbase = g_q8;
#pragma unroll
    for (int r = 0; r < 16; r++) {
        unsigned dst = sbase + r * 512 + lane * 16;
        const unsigned char* src = gbase + (size_t)idx[r] * 512 + lane * 16;
        asm volatile("cp.async.cg.shared.global [%0], [%1], 16;"
                     :: "r"(dst), "l"(src) : "memory");
    }
    asm volatile("cp.async.commit_group;" ::: "memory");
    asm volatile("cp.async.wait_group 0;" ::: "memory");
    __syncwarp();

    // Dots from smem.
    int idot[8];
#pragma unroll
    for (int j = 0; j < 8; j++) {
        uint4 qa = *reinterpret_cast<const uint4*>(
            &sbuf[wslot][j * 512 + lane * 16]);
        uint4 qb = *reinterpret_cast<const uint4*>(
            &sbuf[wslot][(8 + j) * 512 + lane * 16]);
        int t = __dp4a((int)qa.x, (int)qb.x, 0);
        t = __dp4a((int)qa.y, (int)qb.y, t);
        t = __dp4a((int)qa.z, (int)qb.z, t);
        t = __dp4a((int)qa.w, (int)qb.w, t);
        idot[j] = t;
    }

#pragma unroll
    for (int j = 0; j < 8; j++)
        idot[j] = __reduce_add_sync(0xFFFFFFFFu, idot[j]);

    // Lanes 0-7 handle one edge each, in parallel.
    if (lane < 8 && e0 + lane < n_edges) {
        int mydot = idot[0];
        int mia = idx[0], mib = idx[8];
#pragma unroll
        for (int j = 1; j < 8; j++) {
            if (lane == j) { mydot = idot[j]; mia = idx[j]; mib = idx[8 + j]; }
        }

        float2 ca = g_c[mia];
        float2 cb = g_c[mib];
        float dot_n = (float)mydot * ca.x * cb.x;
        float d2 = 2.0f - 2.0f * dot_n
                 + 2.0f * EPS * (ca.y - cb.y)
                 + (float)D * EPS * EPS;
        d2 = fmaxf(d2, 0.0f);
        float v = 1.0f - sqrtf(d2);
        out[e0 + lane] = 1.0f / (1.0f + __expf(-v));
    }
}

// Fallback (fp32 fused, one warp per edge) if n_nodes exceeds static capacity.
__global__ void __launch_bounds__(256)
edge_decoder_f32_kernel(const float* __restrict__ z,
                        const void* __restrict__ edge_index,
                        float* __restrict__ out,
                        int n_edges)
{
    int e = (blockIdx.x * blockDim.x + threadIdx.x) >> 5;
    int lane = threadIdx.x & 31;
    if (e >= n_edges) return;

    long long ia, ib;
    if (g_idx_is64) {
        const long long* ei = (const long long*)edge_index;
        ia = ei[e];
        ib = ei[e + n_edges];
    } else {
        const int* ei = (const int*)edge_index;
        ia = ei[e];
        ib = ei[e + n_edges];
    }

    const float4* A = reinterpret_cast<const float4*>(z + ia * (long long)D);
    const float4* B = reinterpret_cast<const float4*>(z + ib * (long long)D);

    float dot = 0.f, na2 = 0.f, nb2 = 0.f, sa = 0.f, sb = 0.f;
    float4 av[4], bv[4];
#pragma unroll
    for (int j = 0; j < 4; j++) {
        av[j] = A[lane + 32 * j];
        bv[j] = B[lane + 32 * j];
    }
#pragma unroll
    for (int j = 0; j < 4; j++) {
        float4 a = av[j], b = bv[j];
        dot = fmaf(a.x, b.x, dot); dot = fmaf(a.y, b.y, dot);
        dot = fmaf(a.z, b.z, dot); dot = fmaf(a.w, b.w, dot);
        na2 = fmaf(a.x, a.x, na2); na2 = fmaf(a.y, a.y, na2);
        na2 = fmaf(a.z, a.z, na2); na2 = fmaf(a.w, a.w, na2);
        nb2 = fmaf(b.x, b.x, nb2); nb2 = fmaf(b.y, b.y, nb2);
        nb2 = fmaf(b.z, b.z, nb2); nb2 = fmaf(b.w, b.w, nb2);
        sa += a.x + a.y + a.z + a.w;
        sb += b.x + b.y + b.z + b.w;
    }
#pragma unroll
    for (int off = 16; off > 0; off >>= 1) {
        dot += __shfl_xor_sync(0xFFFFFFFFu, dot, off);
        na2 += __shfl_xor_sync(0xFFFFFFFFu, na2, off);
        nb2 += __shfl_xor_sync(0xFFFFFFFFu, nb2, off);
        sa  += __shfl_xor_sync(0xFFFFFFFFu, sa,  off);
        sb  += __shfl_xor_sync(0xFFFFFFFFu, sb,  off);
    }
    if (lane == 0) {
        float inva = rsqrtf(na2);
        float invb = rsqrtf(nb2);
        float d2 = 2.0f - 2.0f * dot * inva * invb
                 + 2.0f * EPS * (sa * inva - sb * invb)
                 + (float)D * EPS * EPS;
        d2 = fmaxf(d2, 0.0f);
        float v = 1.0f - sqrtf(d2);
        out[e] = 1.0f / (1.0f + __expf(-v));
    }
}

extern "C" void kernel_launch(void* const* d_in, const int* in_sizes, int n_in,
                              void* d_out, int out_size)
{
    const float* z = (const float*)d_in[0];
    const void* edge_index = d_in[1];
    float* out = (float*)d_out;

    int n_nodes = in_sizes[0] / D;
    int n_edges = in_sizes[1] / 2;

    if (n_nodes <= NODE_CAP) {
        int ngrid = (n_nodes + 7) / 8;                 // 8 warps/block
        prep_q8_kernel<<<ngrid, 256>>>((const float4*)z,
                                       (const int*)edge_index, n_nodes);
        int ngroups = (n_edges + 7) / 8;               // 8 edges per warp
        int egrid = (ngroups + 3) / 4;                 // 4 warps/block
        edge_decoder_cpasync_kernel<<<egrid, 128>>>(edge_index, out, n_edges);
    } else {
        detect_idx_dtype_kernel<<<1, 32>>>((const int*)edge_index);
        int egrid = (n_edges + 7) / 8;
        edge_decoder_f32_kernel<<<egrid, 256>>>(z, edge_index, out, n_edges);
    }
}